// round 1
// baseline (speedup 1.0000x reference)
#include <cuda_runtime.h>
#include <cuda_bf16.h>

// CrossDepthAttention restructured:
//   q  = current @ Wq^T                                  (GEMM NT, 17.2 GF)
//   qk[m,h,:] = q[m,h,:] @ Wk_h    (Hd x D per head)     (batched GEMM NN, 17.2 GF)
//   logits[m,h,n] = scale * <qk[m,h,:], history[m,n,:]>  (fused attn kernel)
//   attn = softmax_n ; hbar[m,h,:] = sum_n attn*history  (written over qk)
//   out[m,h,:] = hbar[m,h,:] @ Wv_h^T                    (batched GEMM NT, 17.2 GF)
//   final = current + out @ Wo^T                         (GEMM NT + residual, 17.2 GF)
// Exact algebra of the reference; all fp32.

#define D_DIM   1024
#define H_HEADS 16
#define HD      64
#define NPREV   8

// Scratch (allocation-free): module-static device arrays.
__device__ float g_q[8192 * D_DIM];              // q, then reused as attn-out
__device__ float g_qk[8192 * H_HEADS * D_DIM];   // qk, then overwritten by hbar

// ---------------------------------------------------------------------------
// Generic tiled fp32 GEMM.
//   TRANSB=true :  C[m,n] = sum_k A[m,k] * B[n,k]   (both K-major, "NT")
//   TRANSB=false:  C[m,n] = sum_k A[m,k] * B[k,n]   ("NN")
// Batched over blockIdx.z via element strides sA/sB/sC.
// Requires M%BM==0, N%BN==0, K%BK==0 (true for all shapes here).
// ---------------------------------------------------------------------------
template <int BM, int BN, int BK, bool TRANSB, bool RESID>
__global__ __launch_bounds__((BM / 8) * (BN / 8))
void gemm_kernel(const float* __restrict__ A, int lda, long long sA,
                 const float* __restrict__ B, int ldb, long long sB,
                 const float* __restrict__ R,
                 float* __restrict__ C, int ldc, long long sC,
                 int K)
{
    constexpr int TM = 8, TN = 8;
    constexpr int NTH = (BM / TM) * (BN / TN);

    __shared__ float As[BK][BM + 4];
    __shared__ float Bs[BK][BN + 4];

    const int tid = threadIdx.x;
    const int bx = blockIdx.x, by = blockIdx.y, bz = blockIdx.z;

    const float* Ag = A + (long long)bz * sA + (long long)(by * BM) * lda;
    const float* Bg;
    if (TRANSB) Bg = B + (long long)bz * sB + (long long)(bx * BN) * ldb;
    else        Bg = B + (long long)bz * sB + bx * BN;

    const int tx = tid % (BN / TN);
    const int ty = tid / (BN / TN);

    float acc[TM][TN];
#pragma unroll
    for (int i = 0; i < TM; i++)
#pragma unroll
        for (int j = 0; j < TN; j++) acc[i][j] = 0.0f;

    for (int k0 = 0; k0 < K; k0 += BK) {
        // --- load A tile (transpose into As[k][m]) ---
#pragma unroll
        for (int i = tid; i < BM * BK / 4; i += NTH) {
            int row = i / (BK / 4);
            int kc  = i % (BK / 4);
            float4 v = *(const float4*)(Ag + (long long)row * lda + k0 + kc * 4);
            As[kc * 4 + 0][row] = v.x;
            As[kc * 4 + 1][row] = v.y;
            As[kc * 4 + 2][row] = v.z;
            As[kc * 4 + 3][row] = v.w;
        }
        // --- load B tile ---
        if (TRANSB) {
#pragma unroll
            for (int i = tid; i < BN * BK / 4; i += NTH) {
                int row = i / (BK / 4);
                int kc  = i % (BK / 4);
                float4 v = *(const float4*)(Bg + (long long)row * ldb + k0 + kc * 4);
                Bs[kc * 4 + 0][row] = v.x;
                Bs[kc * 4 + 1][row] = v.y;
                Bs[kc * 4 + 2][row] = v.z;
                Bs[kc * 4 + 3][row] = v.w;
            }
        } else {
#pragma unroll
            for (int i = tid; i < BK * BN / 4; i += NTH) {
                int krow = i / (BN / 4);
                int nc   = i % (BN / 4);
                float4 v = *(const float4*)(Bg + (long long)(k0 + krow) * ldb + nc * 4);
                *(float4*)&Bs[krow][nc * 4] = v;
            }
        }
        __syncthreads();

#pragma unroll
        for (int kk = 0; kk < BK; kk++) {
            float a[TM], b[TN];
            *(float4*)&a[0] = *(const float4*)&As[kk][ty * TM];
            *(float4*)&a[4] = *(const float4*)&As[kk][ty * TM + 4];
            *(float4*)&b[0] = *(const float4*)&Bs[kk][tx * TN];
            *(float4*)&b[4] = *(const float4*)&Bs[kk][tx * TN + 4];
#pragma unroll
            for (int i = 0; i < TM; i++)
#pragma unroll
                for (int j = 0; j < TN; j++)
                    acc[i][j] = fmaf(a[i], b[j], acc[i][j]);
        }
        __syncthreads();
    }

    // --- epilogue ---
    float* Cg = C + (long long)bz * sC + (long long)(by * BM + ty * TM) * ldc
                  + bx * BN + tx * TN;
    const float* Rg = nullptr;
    if (RESID)
        Rg = R + (long long)(by * BM + ty * TM) * ldc + bx * BN + tx * TN;

#pragma unroll
    for (int i = 0; i < TM; i++) {
        float4 v0 = make_float4(acc[i][0], acc[i][1], acc[i][2], acc[i][3]);
        float4 v1 = make_float4(acc[i][4], acc[i][5], acc[i][6], acc[i][7]);
        if (RESID) {
            float4 r0 = *(const float4*)(Rg + (long long)i * ldc);
            float4 r1 = *(const float4*)(Rg + (long long)i * ldc + 4);
            v0.x += r0.x; v0.y += r0.y; v0.z += r0.z; v0.w += r0.w;
            v1.x += r1.x; v1.y += r1.y; v1.z += r1.z; v1.w += r1.w;
        }
        *(float4*)(Cg + (long long)i * ldc)     = v0;
        *(float4*)(Cg + (long long)i * ldc + 4) = v1;
    }
}

// ---------------------------------------------------------------------------
// Fused attention: one CTA per (b,s) row m.
//   reads  qk[m,h,:]   (g_qk), history[m,n,:]
//   writes hbar[m,h,:] in place over qk[m,h,:]
// Deterministic tree reductions only.
// ---------------------------------------------------------------------------
__global__ __launch_bounds__(256)
void attn_kernel(const float* __restrict__ hist, float* __restrict__ qkbar)
{
    __shared__ float sh[NPREV][D_DIM];
    __shared__ float red[NPREV][8];
    __shared__ float attn[NPREV];

    const int m    = blockIdx.x;
    const int tid  = threadIdx.x;           // 256 threads
    const int lane = tid & 31;
    const int warp = tid >> 5;

    // load history[m] : NPREV*D contiguous floats
    const float* hg = hist + (long long)m * NPREV * D_DIM;
#pragma unroll 4
    for (int i = tid; i < NPREV * D_DIM / 4; i += 256)
        ((float4*)&sh[0][0])[i] = ((const float4*)hg)[i];
    __syncthreads();

    float* qrow = qkbar + (long long)m * (H_HEADS * D_DIM);
    const int d4 = tid * 4;  // each thread owns one float4 column chunk of D

    for (int h = 0; h < H_HEADS; h++) {
        float4 q4 = *(const float4*)(qrow + h * D_DIM + d4);
        float part[NPREV];
#pragma unroll
        for (int n = 0; n < NPREV; n++) {
            float4 hv = *(const float4*)&sh[n][d4];
            part[n] = q4.x * hv.x + q4.y * hv.y + q4.z * hv.z + q4.w * hv.w;
        }
#pragma unroll
        for (int n = 0; n < NPREV; n++) {
            float v = part[n];
#pragma unroll
            for (int o = 16; o > 0; o >>= 1)
                v += __shfl_xor_sync(0xffffffffu, v, o);
            if (lane == 0) red[n][warp] = v;
        }
        __syncthreads();
        if (tid == 0) {
            float lg[NPREV];
            float mx = -1e30f;
#pragma unroll
            for (int n = 0; n < NPREV; n++) {
                float s = 0.0f;
#pragma unroll
                for (int w = 0; w < 8; w++) s += red[n][w];
                lg[n] = s * 0.125f;   // 1/sqrt(Hd=64)
                mx = fmaxf(mx, lg[n]);
            }
            float den = 0.0f;
#pragma unroll
            for (int n = 0; n < NPREV; n++) { lg[n] = expf(lg[n] - mx); den += lg[n]; }
            float inv = 1.0f / den;
#pragma unroll
            for (int n = 0; n < NPREV; n++) attn[n] = lg[n] * inv;
        }
        __syncthreads();
        // hbar = sum_n attn[n] * history[n]; overwrite qk[m,h,:]
        float4 a4 = make_float4(0.f, 0.f, 0.f, 0.f);
#pragma unroll
        for (int n = 0; n < NPREV; n++) {
            float w = attn[n];
            float4 hv = *(const float4*)&sh[n][d4];
            a4.x = fmaf(w, hv.x, a4.x);
            a4.y = fmaf(w, hv.y, a4.y);
            a4.z = fmaf(w, hv.z, a4.z);
            a4.w = fmaf(w, hv.w, a4.w);
        }
        *(float4*)(qrow + h * D_DIM + d4) = a4;
        __syncthreads();
    }
}

// ---------------------------------------------------------------------------
extern "C" void kernel_launch(void* const* d_in, const int* in_sizes, int n_in,
                              void* d_out, int out_size)
{
    const float* cur  = (const float*)d_in[0];   // (B,S,D)     = (M, 1024)
    const float* hist = (const float*)d_in[1];   // (B,S,N,D)   = (M, 8, 1024)
    const float* Wq   = (const float*)d_in[2];
    const float* Wk   = (const float*)d_in[3];
    const float* Wv   = (const float*)d_in[4];
    const float* Wo   = (const float*)d_in[5];
    float* out = (float*)d_out;

    const int D = D_DIM;
    const int M = in_sizes[0] / D;               // 8192

    float *q = nullptr, *qk = nullptr;
    cudaGetSymbolAddress((void**)&q,  g_q);
    cudaGetSymbolAddress((void**)&qk, g_qk);

    // 1) q = current @ Wq^T        : NT, M x 1024 x 1024
    gemm_kernel<128, 128, 16, true, false>
        <<<dim3(D / 128, M / 128, 1), 256>>>(
            cur, D, 0, Wq, D, 0, nullptr, q, D, 0, D);

    // 2) qk_h = q_h @ Wk_h         : NN batched over h, M x 1024 x 64
    gemm_kernel<128, 128, 16, false, false>
        <<<dim3(D / 128, M / 128, H_HEADS), 256>>>(
            q, D, HD,                  // A = q[:, h*64 : h*64+64]
            Wk, D, (long long)HD * D,  // B = Wk[h*64 : h*64+64, :]
            nullptr,
            qk, H_HEADS * D, D,        // C = qk[:, h, :]
            HD);

    // 3) fused attention: logits -> softmax -> hbar (in place over qk)
    attn_kernel<<<M, 256>>>(hist, qk);

    // 4) out_h = hbar_h @ Wv_h^T   : NT batched over h, M x 64 x 1024
    gemm_kernel<128, 64, 16, true, false>
        <<<dim3(1, M / 128, H_HEADS), 128>>>(
            qk, H_HEADS * D, D,        // A = hbar[:, h, :]
            Wv, D, (long long)HD * D,  // B = Wv[h*64 : h*64+64, :]
            nullptr,
            q, D, HD,                  // C = out[:, h*64 : h*64+64] (reuse g_q)
            D);

    // 5) final = current + out @ Wo^T : NT + residual, M x 1024 x 1024
    gemm_kernel<128, 128, 16, true, true>
        <<<dim3(D / 128, M / 128, 1), 256>>>(
            q, D, 0, Wo, D, 0, cur, out, D, 0, D);
}

// round 4
// speedup vs baseline: 2.3040x; 2.3040x over previous
#include <cuda_runtime.h>
#include <cuda_bf16.h>
#include <cstdint>

// ============================================================================
// CrossDepthAttention via mma.sync (m16n8k8 tf32) — base-target tensor cores.
//   K1: q    = cur @ Wq^T                       (8192 x 1024 x 1024, NT)
//   K2: qk_h = q_h @ Wk_h    (NN, K=64, x16)    -> bf16
//   K3: fused attention: logits/softmax/hbar    qk(bf16) -> hbar(fp32)
//   K4: out_h = hbar_h @ Wv_h^T (NT, N=64, x16) -> fp32
//   K5: final = cur + out @ Wo^T                (NT + residual)
// ============================================================================

#define D_DIM   1024
#define H_HEADS 16
#define HD      64
#define NPREV   8
#define M_MAX   8192

__device__ float         g_q[M_MAX * D_DIM];                       // q, then out
__device__ __nv_bfloat16 g_qk[(size_t)M_MAX * H_HEADS * D_DIM];    // qk (bf16)
__device__ float         g_hbar[(size_t)M_MAX * H_HEADS * D_DIM];  // hbar (fp32)

// ---------------------------------------------------------------------------
__device__ __forceinline__ uint32_t smem_u32(const void* p) {
    uint32_t a;
    asm("{ .reg .u64 t; cvta.to.shared.u64 t, %1; cvt.u32.u64 %0, t; }"
        : "=r"(a) : "l"(p));
    return a;
}
__device__ __forceinline__ void cp16(uint32_t s, const void* g) {
    asm volatile("cp.async.cg.shared.global [%0], [%1], 16;\n" :: "r"(s), "l"(g));
}
__device__ __forceinline__ void cp_commit() {
    asm volatile("cp.async.commit_group;\n" ::: "memory");
}
template <int N> __device__ __forceinline__ void cp_wait() {
    asm volatile("cp.async.wait_group %0;\n" :: "n"(N) : "memory");
}
__device__ __forceinline__ void mma_tf32(float* c, const uint32_t* a,
                                         const uint32_t* b) {
    asm volatile(
        "mma.sync.aligned.m16n8k8.row.col.f32.tf32.tf32.f32 "
        "{%0,%1,%2,%3}, {%4,%5,%6,%7}, {%8,%9}, {%0,%1,%2,%3};\n"
        : "+f"(c[0]), "+f"(c[1]), "+f"(c[2]), "+f"(c[3])
        : "r"(a[0]), "r"(a[1]), "r"(a[2]), "r"(a[3]), "r"(b[0]), "r"(b[1]));
}

// ---------------------------------------------------------------------------
// Tiled mma.sync GEMM: C[m,n] = sum_k A[m,k] * B'[n,k]
//   B_NN=false : B'[n,k] = B[n*ldb + k]   (NT, k contiguous -> cp.async)
//   B_NN=true  : B'[n,k] = B[k*ldb + n]   (NN, manual transpose STS)
// CTA tile 128 x BN x 32. 256 threads (8 warps). SMEM stride 36 (pad 4):
// 36 mod 32 == 4 -> conflict-free fragment LDS for the quad pattern.
// ---------------------------------------------------------------------------
template <int BN, bool B_NN, bool OUT_BF16, bool RESID>
__global__ void __launch_bounds__(256)
gemm_mma(const float* __restrict__ A, int lda, long long sA,
         const float* __restrict__ B, int ldb, long long sB,
         const float* __restrict__ R,
         void* __restrict__ C, int ldc, long long sC,
         int K)
{
    constexpr int WM = (BN == 128) ? 2 : 4;        // warps along M
    constexpr int MT = 8 / WM;                     // 16-row mma tiles per warp
    constexpr int A_FLOATS = 128 * 36;
    constexpr int B_FLOATS = BN * 36;

    extern __shared__ float smem_f[];
    const uint32_t sbase = smem_u32(smem_f);

    const int tid = threadIdx.x;
    const int wid = tid >> 5, lane = tid & 31;
    const int wm = wid % WM, wn = wid / WM;
    const int bx = blockIdx.x, by = blockIdx.y, bz = blockIdx.z;

    const float* Af = A + (long long)bz * sA + (size_t)(by * 128) * lda;
    const float* Bg = B_NN ? (B + (long long)bz * sB + bx * BN)
                           : (B + (long long)bz * sB + (size_t)(bx * BN) * ldb);

    auto fill = [&](int buf, int k0) {
        const uint32_t As_b = sbase + (uint32_t)(buf * A_FLOATS) * 4u;
        const uint32_t Bs_b = sbase + (uint32_t)(2 * A_FLOATS + buf * B_FLOATS) * 4u;
        // ---- A tile: 128 rows x 32 floats, cp.async 16B chunks ----
#pragma unroll
        for (int p = 0; p < 4; ++p) {
            int ch = tid + p * 256;
            int row = ch >> 3, c4 = ch & 7;
            cp16(As_b + (uint32_t)(row * 36 + c4 * 4) * 4u,
                 Af + (size_t)row * lda + k0 + c4 * 4);
        }
        // ---- B tile ----
        if (!B_NN) {
#pragma unroll
            for (int p = 0; p < BN * 8 / 256; ++p) {
                int ch = tid + p * 256;
                int row = ch >> 3, c4 = ch & 7;
                cp16(Bs_b + (uint32_t)(row * 36 + c4 * 4) * 4u,
                     Bg + (size_t)row * ldb + k0 + c4 * 4);
            }
        } else {
            float* Bs_p = smem_f + 2 * A_FLOATS + buf * B_FLOATS;
#pragma unroll
            for (int p = 0; p < BN * 32 / 256; ++p) {
                int idx = tid + p * 256;
                int n = idx % BN, k = idx / BN;
                Bs_p[n * 36 + k] = Bg[(size_t)(k0 + k) * ldb + n];
            }
        }
    };

    float acc[MT][4][4];
#pragma unroll
    for (int mt = 0; mt < MT; ++mt)
#pragma unroll
        for (int nt = 0; nt < 4; ++nt)
#pragma unroll
            for (int j = 0; j < 4; ++j) acc[mt][nt][j] = 0.0f;

    const int a_off = (wm * (128 / WM) + (lane >> 2)) * 36 + (lane & 3);
    const int b_off = (wn * 32 + (lane >> 2)) * 36 + (lane & 3);

    const int NC = K / 32;
    fill(0, 0);
    cp_commit();

    for (int c = 0; c < NC; ++c) {
        if (c + 1 < NC) { fill((c + 1) & 1, (c + 1) * 32); cp_commit(); cp_wait<1>(); }
        else            { cp_wait<0>(); }
        __syncthreads();

        const int buf = c & 1;
        const float* As_c = smem_f + buf * A_FLOATS;
        const float* Bs_c = smem_f + 2 * A_FLOATS + buf * B_FLOATS;

#pragma unroll
        for (int s = 0; s < 4; ++s) {
            uint32_t af[MT][4];
#pragma unroll
            for (int mt = 0; mt < MT; ++mt) {
                const float* p = As_c + a_off + mt * 16 * 36 + s * 8;
                af[mt][0] = __float_as_uint(p[0]);
                af[mt][1] = __float_as_uint(p[8 * 36]);
                af[mt][2] = __float_as_uint(p[4]);
                af[mt][3] = __float_as_uint(p[8 * 36 + 4]);
            }
            uint32_t bf[4][2];
#pragma unroll
            for (int nt = 0; nt < 4; ++nt) {
                const float* p = Bs_c + b_off + nt * 8 * 36 + s * 8;
                bf[nt][0] = __float_as_uint(p[0]);
                bf[nt][1] = __float_as_uint(p[4]);
            }
#pragma unroll
            for (int mt = 0; mt < MT; ++mt)
#pragma unroll
                for (int nt = 0; nt < 4; ++nt)
                    mma_tf32(acc[mt][nt], af[mt], bf[nt]);
        }
        __syncthreads();
    }

    // ---- epilogue ----
    const int row0 = by * 128 + wm * (128 / WM) + (lane >> 2);
    const int coll = wn * 32 + (lane & 3) * 2;
#pragma unroll
    for (int mt = 0; mt < MT; ++mt) {
        const int m = row0 + mt * 16;
#pragma unroll
        for (int nt = 0; nt < 4; ++nt) {
            const int n = bx * BN + coll + nt * 8;
            if (!OUT_BF16) {
                float* Cg = (float*)C + (long long)bz * sC;
                float2 v0 = make_float2(acc[mt][nt][0], acc[mt][nt][1]);
                float2 v1 = make_float2(acc[mt][nt][2], acc[mt][nt][3]);
                if (RESID) {
                    float2 r0 = *(const float2*)(R + (size_t)m * ldc + n);
                    float2 r1 = *(const float2*)(R + (size_t)(m + 8) * ldc + n);
                    v0.x += r0.x; v0.y += r0.y;
                    v1.x += r1.x; v1.y += r1.y;
                }
                *(float2*)(Cg + (size_t)m * ldc + n)       = v0;
                *(float2*)(Cg + (size_t)(m + 8) * ldc + n) = v1;
            } else {
                __nv_bfloat16* Cg = (__nv_bfloat16*)C + (long long)bz * sC;
                __nv_bfloat162 p0 = __float22bfloat162_rn(
                    make_float2(acc[mt][nt][0], acc[mt][nt][1]));
                __nv_bfloat162 p1 = __float22bfloat162_rn(
                    make_float2(acc[mt][nt][2], acc[mt][nt][3]));
                *(__nv_bfloat162*)(Cg + (size_t)m * ldc + n)       = p0;
                *(__nv_bfloat162*)(Cg + (size_t)(m + 8) * ldc + n) = p1;
            }
        }
    }
}

// ---------------------------------------------------------------------------
// Fused attention: one CTA per row m. History in registers (8 x float4 per
// thread), qk read bf16, hbar written fp32 to g_hbar.
// ---------------------------------------------------------------------------
__global__ void __launch_bounds__(256) attn_kernel(
    const float* __restrict__ hist, const __nv_bfloat16* __restrict__ qk,
    float* __restrict__ hbar)
{
    __shared__ float red[NPREV][8];
    __shared__ float attn_s[NPREV];

    const int m    = blockIdx.x;
    const int tid  = threadIdx.x;
    const int lane = tid & 31;
    const int warp = tid >> 5;

    float4 hv[NPREV];
    const float* hg = hist + (size_t)m * NPREV * D_DIM + tid * 4;
#pragma unroll
    for (int n = 0; n < NPREV; n++)
        hv[n] = *(const float4*)(hg + n * D_DIM);

    const __nv_bfloat16* qrow = qk + (size_t)m * (H_HEADS * D_DIM) + tid * 4;
    float* orow = hbar + (size_t)m * (H_HEADS * D_DIM) + tid * 4;

    for (int h = 0; h < H_HEADS; h++) {
        uint2 raw = *(const uint2*)(qrow + h * D_DIM);
        float2 qa = __bfloat1622float2(*reinterpret_cast<__nv_bfloat162*>(&raw.x));
        float2 qb = __bfloat1622float2(*reinterpret_cast<__nv_bfloat162*>(&raw.y));

        float part[NPREV];
#pragma unroll
        for (int n = 0; n < NPREV; n++)
            part[n] = qa.x * hv[n].x + qa.y * hv[n].y + qb.x * hv[n].z + qb.y * hv[n].w;
#pragma unroll
        for (int n = 0; n < NPREV; n++) {
            float v = part[n];
#pragma unroll
            for (int o = 16; o > 0; o >>= 1)
                v += __shfl_xor_sync(0xffffffffu, v, o);
            if (lane == 0) red[n][warp] = v;
        }
        __syncthreads();
        if (tid == 0) {
            float lg[NPREV]; float mx = -1e30f;
#pragma unroll
            for (int n = 0; n < NPREV; n++) {
                float s = 0.0f;
#pragma unroll
                for (int w = 0; w < 8; w++) s += red[n][w];
                lg[n] = s * 0.125f;              // 1/sqrt(Hd=64)
                mx = fmaxf(mx, lg[n]);
            }
            float den = 0.0f;
#pragma unroll
            for (int n = 0; n < NPREV; n++) { lg[n] = expf(lg[n] - mx); den += lg[n]; }
            float inv = 1.0f / den;
#pragma unroll
            for (int n = 0; n < NPREV; n++) attn_s[n] = lg[n] * inv;
        }
        __syncthreads();
        float4 a4 = make_float4(0.f, 0.f, 0.f, 0.f);
#pragma unroll
        for (int n = 0; n < NPREV; n++) {
            float w = attn_s[n];
            a4.x = fmaf(w, hv[n].x, a4.x);
            a4.y = fmaf(w, hv[n].y, a4.y);
            a4.z = fmaf(w, hv[n].z, a4.z);
            a4.w = fmaf(w, hv[n].w, a4.w);
        }
        *(float4*)(orow + h * D_DIM) = a4;
    }
}

// ---------------------------------------------------------------------------
extern "C" void kernel_launch(void* const* d_in, const int* in_sizes, int n_in,
                              void* d_out, int out_size)
{
    const float* cur  = (const float*)d_in[0];
    const float* hist = (const float*)d_in[1];
    const float* Wq   = (const float*)d_in[2];
    const float* Wk   = (const float*)d_in[3];
    const float* Wv   = (const float*)d_in[4];
    const float* Wo   = (const float*)d_in[5];
    float* out = (float*)d_out;

    const int D = D_DIM;
    const int M = in_sizes[0] / D;   // 8192

    float* q = nullptr;
    __nv_bfloat16* qk = nullptr;
    float* hbar = nullptr;
    cudaGetSymbolAddress((void**)&q,    g_q);
    cudaGetSymbolAddress((void**)&qk,   g_qk);
    cudaGetSymbolAddress((void**)&hbar, g_hbar);

    constexpr int SM128 = (2 * 128 * 36 + 2 * 128 * 36) * 4;   // 73728
    constexpr int SM64  = (2 * 128 * 36 + 2 * 64 * 36) * 4;    // 55296

    cudaFuncSetAttribute(gemm_mma<128, false, false, false>,
                         cudaFuncAttributeMaxDynamicSharedMemorySize, SM128);
    cudaFuncSetAttribute(gemm_mma<128, true,  true,  false>,
                         cudaFuncAttributeMaxDynamicSharedMemorySize, SM128);
    cudaFuncSetAttribute(gemm_mma<64,  false, false, false>,
                         cudaFuncAttributeMaxDynamicSharedMemorySize, SM64);
    cudaFuncSetAttribute(gemm_mma<128, false, false, true>,
                         cudaFuncAttributeMaxDynamicSharedMemorySize, SM128);

    // K1: q = cur @ Wq^T
    gemm_mma<128, false, false, false>
        <<<dim3(D / 128, M / 128, 1), 256, SM128>>>(
            cur, D, 0, Wq, D, 0, nullptr, q, D, 0, D);

    // K2: qk_h = q_h @ Wk_h  (NN, K=64, x16 heads) -> bf16
    gemm_mma<128, true, true, false>
        <<<dim3(D / 128, M / 128, H_HEADS), 256, SM128>>>(
            q, D, HD,
            Wk, D, (long long)HD * D,
            nullptr,
            qk, H_HEADS * D, D,
            HD);

    // K3: attention
    attn_kernel<<<M, 256>>>(hist, qk, hbar);

    // K4: out_h = hbar_h @ Wv_h^T (NT, N=64, x16) -> g_q
    gemm_mma<64, false, false, false>
        <<<dim3(1, M / 128, H_HEADS), 256, SM64>>>(
            hbar, H_HEADS * D, D,
            Wv, D, (long long)HD * D,
            nullptr,
            q, D, HD,
            D);

    // K5: final = cur + out @ Wo^T
    gemm_mma<128, false, false, true>
        <<<dim3(D / 128, M / 128, 1), 256, SM128>>>(
            q, D, 0, Wo, D, 0, cur, out, D, 0, D);
}